// round 15
// baseline (speedup 1.0000x reference)
#include <cuda_runtime.h>
#include <math.h>
#include <stdint.h>

// ---------------- problem constants ----------------
#define B_   8
#define S_   64
#define N_   1024
#define C_   16
#define H_   128
#define P_   10
#define ROWS (B_ * N_)    // 8192
#define DT_  7.0f

#define PRED_ELEMS   (B_ * S_ * N_ * C_)       // 8388608
#define INTERP_ELEMS (S_ * B_ * N_ * H_)       // 67108864

// ---------------- device scratch ----------------
__device__ float g_sol[P_ * ROWS * H_];    // raw trajectory ~42MB
__device__ float g_ssan[2 * ROWS * H_];    // sanitized state, double-buffered
__device__ float g_y[P_ * ROWS * H_];      // sol@dec_w1+b1 ~42MB
__device__ float g_dyn[ROWS * H_];
__device__ float g_logits[ROWS];
__device__ float g_attn[ROWS];
__device__ int   g_nbr[N_ * N_];
__device__ int   g_cnt[N_];
__device__ float g_invdeg[N_];

// ---------------- helpers ----------------
__device__ __forceinline__ float sigmoidf_(float v) { return 1.0f / (1.0f + __expf(-v)); }
__device__ __forceinline__ float siluf_(float v)    { return v * sigmoidf_(v); }
__device__ __forceinline__ float tanh_fast(float x) {
    float y;
    asm("tanh.approx.f32 %0, %1;" : "=f"(y) : "f"(x));
    return y;
}
__device__ __forceinline__ float sanf_(float v) {
    if (isnan(v)) return 0.0f;
    if (isinf(v)) return v > 0.0f ? 3.402823466e38f : -3.402823466e38f;
    return v;
}

__device__ __forceinline__ float blk_sum128(float v, float* red) {
    #pragma unroll
    for (int o = 16; o > 0; o >>= 1) v += __shfl_down_sync(0xffffffffu, v, o);
    __syncthreads();
    if ((threadIdx.x & 31) == 0) red[threadIdx.x >> 5] = v;
    __syncthreads();
    return red[0] + red[1] + red[2] + red[3];
}

// 256-thread block reductions (red8 must hold >= 8 floats)
__device__ __forceinline__ float blk_sum256(float v, float* red8) {
    #pragma unroll
    for (int o = 16; o > 0; o >>= 1) v += __shfl_down_sync(0xffffffffu, v, o);
    __syncthreads();
    if ((threadIdx.x & 31) == 0) red8[threadIdx.x >> 5] = v;
    __syncthreads();
    float s = 0.0f;
    #pragma unroll
    for (int w = 0; w < 8; ++w) s += red8[w];
    return s;
}
__device__ __forceinline__ float blk_max256(float v, float* red8) {
    #pragma unroll
    for (int o = 16; o > 0; o >>= 1) v = fmaxf(v, __shfl_down_sync(0xffffffffu, v, o));
    __syncthreads();
    if ((threadIdx.x & 31) == 0) red8[threadIdx.x >> 5] = v;
    __syncthreads();
    float s = red8[0];
    #pragma unroll
    for (int w = 1; w < 8; ++w) s = fmaxf(s, red8[w]);
    return s;
}

// warp sum, deterministic tree, result broadcast to all lanes
__device__ __forceinline__ float warp_sum_bcast(float v) {
    #pragma unroll
    for (int o = 16; o > 0; o >>= 1) v += __shfl_down_sync(0xffffffffu, v, o);
    return __shfl_sync(0xffffffffu, v, 0);
}

// ---------------- kernel 1: adjacency -> neighbor lists ----------------
__global__ void build_graph_kernel(const float* __restrict__ adj) {
    int m = blockIdx.x;
    int l = threadIdx.x;
    float deg = 0.0f;
    int cnt = 0;
    for (int base = 0; base < N_; base += 32) {
        float a = adj[m * N_ + base + l];
        bool nz = (a != 0.0f);
        deg += a;
        unsigned mask = __ballot_sync(0xffffffffu, nz);
        int pre = __popc(mask & ((1u << l) - 1u));
        if (nz) g_nbr[m * N_ + cnt + pre] = base + l;
        cnt += __popc(mask);
    }
    #pragma unroll
    for (int o = 16; o > 0; o >>= 1) deg += __shfl_down_sync(0xffffffffu, deg, o);
    if (l == 0) {
        g_cnt[m] = cnt;
        g_invdeg[m] = 1.0f / (deg + 1e-8f);
    }
}

// ---------------- kernel 2: encoder -> sol[0], ssan[0], logits[0] ----------------
__global__ __launch_bounds__(128) void encoder_kernel(
    const float* __restrict__ x, const float* __restrict__ enc_w,
    const float* __restrict__ enc_b, const float* __restrict__ enc_g,
    const float* __restrict__ enc_beta,
    const float* __restrict__ attn_w, const float* __restrict__ attn_b)
{
    int row = blockIdx.x;
    int b = row >> 10, n = row & 1023;
    int j = threadIdx.x;
    __shared__ float xr[C_];
    __shared__ float red[4];
    if (j < C_) xr[j] = x[(size_t)b * (S_ * N_ * C_) + (size_t)n * C_ + j];
    __syncthreads();
    float acc = enc_b[j];
    #pragma unroll
    for (int c = 0; c < C_; ++c) acc = fmaf(xr[c], enc_w[c * H_ + j], acc);
    float mean = blk_sum128(acc, red) * (1.0f / H_);
    float d = acc - mean;
    float var = blk_sum128(d * d, red) * (1.0f / H_);
    float yn = d * rsqrtf(var + 1e-5f) * enc_g[j] + enc_beta[j];
    float z = siluf_(yn);
    g_sol[(size_t)row * H_ + j] = z;
    g_ssan[(size_t)row * H_ + j] = z;
    float lgt = blk_sum128(z * attn_w[j], red);
    if (j == 0) g_logits[row] = lgt + attn_b[0];
}

// ---------------- kernel 3: dyn MLP v4 (verified best: ~42.5us/step) ----------------
__global__ __launch_bounds__(256) void step_dyn_v4(
    int p,
    const float* __restrict__ w1, const float* __restrict__ b1,
    const float* __restrict__ lgm, const float* __restrict__ lbt,
    const float* __restrict__ w2, const float* __restrict__ b2)
{
    __shared__ float buf[32 * 132];
    __shared__ float psum[32 * 16];
    __shared__ float psq[32 * 16];
    __shared__ float s_mean[32];
    __shared__ float s_rstd[32];
    __shared__ float red8[8];

    int row0 = blockIdx.x << 5;
    int tid = threadIdx.x;
    int tx = tid & 15;
    int kz = (tid >> 4) & 1;
    int ty = tid >> 5;
    int kbase = kz << 6;

    const float* ssan = g_ssan + (size_t)(p & 1) * (ROWS * H_);

    if ((row0 & 1023) == 0) {
        int b = row0 >> 10;
        const float* lg = &g_logits[b * N_];
        float lv[4];
        float mloc = -INFINITY;
        #pragma unroll
        for (int i = 0; i < 4; ++i) { lv[i] = lg[tid + i * 256]; mloc = fmaxf(mloc, lv[i]); }
        float mx = blk_max256(mloc, red8);
        float sloc = 0.0f;
        #pragma unroll
        for (int i = 0; i < 4; ++i) { lv[i] = expf(lv[i] - mx); sloc += lv[i]; }
        float tot = blk_sum256(sloc, red8);
        float inv = 1.0f / tot;
        #pragma unroll
        for (int i = 0; i < 4; ++i) g_attn[b * N_ + tid + i * 256] = lv[i] * inv;
    }

    {
        int r = tid >> 3, c0 = (tid & 7) << 4;
        const float4* pp = (const float4*)(ssan + (size_t)(row0 + r) * H_ + c0);
        #pragma unroll
        for (int q = 0; q < 4; ++q) {
            float4 v = pp[q];
            int k = c0 + q * 4;
            buf[(k + 0) * 32 + r] = v.x;
            buf[(k + 1) * 32 + r] = v.y;
            buf[(k + 2) * 32 + r] = v.z;
            buf[(k + 3) * 32 + r] = v.w;
        }
    }
    __syncthreads();

    float acc[4][8];
    if (kz == 0) {
        float4 bi0 = *(const float4*)(b1 + tx * 8);
        float4 bi1 = *(const float4*)(b1 + tx * 8 + 4);
        #pragma unroll
        for (int i = 0; i < 4; ++i) {
            acc[i][0] = bi0.x; acc[i][1] = bi0.y; acc[i][2] = bi0.z; acc[i][3] = bi0.w;
            acc[i][4] = bi1.x; acc[i][5] = bi1.y; acc[i][6] = bi1.z; acc[i][7] = bi1.w;
        }
    } else {
        #pragma unroll
        for (int i = 0; i < 4; ++i)
            #pragma unroll
            for (int j = 0; j < 8; ++j) acc[i][j] = 0.0f;
    }
    const float4* wv = (const float4*)w1;
    #pragma unroll 4
    for (int k = 0; k < 64; ++k) {
        int kk = kbase + k;
        float4 a0 = *(const float4*)&buf[kk * 32 + ty * 4];
        float4 w0 = wv[kk * 32 + tx * 2];
        float4 w1v = wv[kk * 32 + tx * 2 + 1];
        float av[4] = {a0.x, a0.y, a0.z, a0.w};
        float bv[8] = {w0.x, w0.y, w0.z, w0.w, w1v.x, w1v.y, w1v.z, w1v.w};
        #pragma unroll
        for (int i = 0; i < 4; ++i)
            #pragma unroll
            for (int j = 0; j < 8; ++j)
                acc[i][j] = fmaf(av[i], bv[j], acc[i][j]);
    }
    __syncthreads();
    if (kz == 1) {
        #pragma unroll
        for (int i = 0; i < 4; ++i) {
            float4* dst = (float4*)&buf[(ty * 4 + i) * 132 + tx * 8];
            dst[0] = make_float4(acc[i][0], acc[i][1], acc[i][2], acc[i][3]);
            dst[1] = make_float4(acc[i][4], acc[i][5], acc[i][6], acc[i][7]);
        }
    }
    __syncthreads();
    if (kz == 0) {
        #pragma unroll
        for (int i = 0; i < 4; ++i) {
            const float4* src = (const float4*)&buf[(ty * 4 + i) * 132 + tx * 8];
            float4 p0 = src[0], p1 = src[1];
            acc[i][0] += p0.x; acc[i][1] += p0.y; acc[i][2] += p0.z; acc[i][3] += p0.w;
            acc[i][4] += p1.x; acc[i][5] += p1.y; acc[i][6] += p1.z; acc[i][7] += p1.w;
            float sm = 0.0f, sq = 0.0f;
            #pragma unroll
            for (int j = 0; j < 8; ++j) { sm += acc[i][j]; sq = fmaf(acc[i][j], acc[i][j], sq); }
            psum[(ty * 4 + i) * 16 + tx] = sm;
            psq [(ty * 4 + i) * 16 + tx] = sq;
        }
    }
    __syncthreads();
    if (tid < 32) {
        float sm = 0.0f, sq = 0.0f;
        #pragma unroll
        for (int t = 0; t < 16; ++t) { sm += psum[tid * 16 + t]; sq += psq[tid * 16 + t]; }
        float mean = sm * (1.0f / H_);
        float var  = fmaxf(sq * (1.0f / H_) - mean * mean, 0.0f);
        s_mean[tid] = mean;
        s_rstd[tid] = rsqrtf(var + 1e-5f);
    }
    __syncthreads();

    if (kz == 0) {
        float4 g0 = *(const float4*)(lgm + tx * 8);
        float4 g1 = *(const float4*)(lgm + tx * 8 + 4);
        float4 e0 = *(const float4*)(lbt + tx * 8);
        float4 e1 = *(const float4*)(lbt + tx * 8 + 4);
        float gj[8] = {g0.x, g0.y, g0.z, g0.w, g1.x, g1.y, g1.z, g1.w};
        float ej[8] = {e0.x, e0.y, e0.z, e0.w, e1.x, e1.y, e1.z, e1.w};
        #pragma unroll
        for (int i = 0; i < 4; ++i) {
            int r = ty * 4 + i;
            float m = s_mean[r], rs = s_rstd[r];
            float hv[8];
            #pragma unroll
            for (int j = 0; j < 8; ++j)
                hv[j] = siluf_((acc[i][j] - m) * rs * gj[j] + ej[j]);
            float4* dst = (float4*)&buf[r * 132 + tx * 8];
            dst[0] = make_float4(hv[0], hv[1], hv[2], hv[3]);
            dst[1] = make_float4(hv[4], hv[5], hv[6], hv[7]);
        }
    }
    __syncthreads();

    if (kz == 0) {
        float4 bi0 = *(const float4*)(b2 + tx * 8);
        float4 bi1 = *(const float4*)(b2 + tx * 8 + 4);
        #pragma unroll
        for (int i = 0; i < 4; ++i) {
            acc[i][0] = bi0.x; acc[i][1] = bi0.y; acc[i][2] = bi0.z; acc[i][3] = bi0.w;
            acc[i][4] = bi1.x; acc[i][5] = bi1.y; acc[i][6] = bi1.z; acc[i][7] = bi1.w;
        }
    } else {
        #pragma unroll
        for (int i = 0; i < 4; ++i)
            #pragma unroll
            for (int j = 0; j < 8; ++j) acc[i][j] = 0.0f;
    }
    const float4* wv2 = (const float4*)w2;
    #pragma unroll 4
    for (int k = 0; k < 64; ++k) {
        int kk = kbase + k;
        float4 w0 = wv2[kk * 32 + tx * 2];
        float4 w1v = wv2[kk * 32 + tx * 2 + 1];
        float bv[8] = {w0.x, w0.y, w0.z, w0.w, w1v.x, w1v.y, w1v.z, w1v.w};
        float av[4];
        #pragma unroll
        for (int i = 0; i < 4; ++i) av[i] = buf[(ty * 4 + i) * 132 + kk];
        #pragma unroll
        for (int i = 0; i < 4; ++i)
            #pragma unroll
            for (int j = 0; j < 8; ++j)
                acc[i][j] = fmaf(av[i], bv[j], acc[i][j]);
    }
    __syncthreads();
    if (kz == 1) {
        #pragma unroll
        for (int i = 0; i < 4; ++i) {
            float4* dst = (float4*)&buf[(ty * 4 + i) * 132 + tx * 8];
            dst[0] = make_float4(acc[i][0], acc[i][1], acc[i][2], acc[i][3]);
            dst[1] = make_float4(acc[i][4], acc[i][5], acc[i][6], acc[i][7]);
        }
    }
    __syncthreads();
    if (kz == 0) {
        #pragma unroll
        for (int i = 0; i < 4; ++i) {
            const float4* src = (const float4*)&buf[(ty * 4 + i) * 132 + tx * 8];
            float4 p0 = src[0], p1 = src[1];
            float o[8];
            o[0] = tanh_fast(acc[i][0] + p0.x);
            o[1] = tanh_fast(acc[i][1] + p0.y);
            o[2] = tanh_fast(acc[i][2] + p0.z);
            o[3] = tanh_fast(acc[i][3] + p0.w);
            o[4] = tanh_fast(acc[i][4] + p1.x);
            o[5] = tanh_fast(acc[i][5] + p1.y);
            o[6] = tanh_fast(acc[i][6] + p1.z);
            o[7] = tanh_fast(acc[i][7] + p1.w);
            float4* dst = (float4*)&g_dyn[(size_t)(row0 + ty * 4 + i) * H_ + tx * 8];
            dst[0] = make_float4(o[0], o[1], o[2], o[3]);
            dst[1] = make_float4(o[4], o[5], o[6], o[7]);
        }
    }
}

// ---------------- kernel 4: update, warp-per-row (grid 2048) ----------------
__global__ __launch_bounds__(128) void step_update_v2(
    int p, const float* __restrict__ diff_scale, const float* __restrict__ time_scale,
    const float* __restrict__ attn_w, const float* __restrict__ attn_b)
{
    __shared__ float attn_sh[N_];

    int row0 = blockIdx.x << 2;
    int b = row0 >> 10;
    int tid = threadIdx.x;
    int w = tid >> 5;
    int l = tid & 31;

    {
        const float4* src = (const float4*)(g_attn + b * N_);
        float4* dst = (float4*)attn_sh;
        for (int i = tid; i < N_ / 4; i += 128) dst[i] = src[i];
    }
    __syncthreads();

    const float* ssan = g_ssan + (size_t)(p & 1) * (ROWS * H_);
    float* ssan_next  = g_ssan + (size_t)((p + 1) & 1) * (ROWS * H_);

    int row = row0 + w;
    int m = row & 1023;
    int cnt = g_cnt[m];
    const int* nb = &g_nbr[m * N_];
    const float* sb = ssan + (size_t)b * N_ * H_;

    float d0 = 0.0f, d1 = 0.0f, d2 = 0.0f, d3 = 0.0f;
    int it = 0;
    for (; it + 4 <= cnt; it += 4) {
        int n0 = nb[it], n1 = nb[it + 1], n2 = nb[it + 2], n3 = nb[it + 3];
        float a0 = attn_sh[n0], a1 = attn_sh[n1], a2 = attn_sh[n2], a3 = attn_sh[n3];
        float4 v0 = *(const float4*)(sb + (size_t)n0 * H_ + l * 4);
        float4 v1 = *(const float4*)(sb + (size_t)n1 * H_ + l * 4);
        float4 v2 = *(const float4*)(sb + (size_t)n2 * H_ + l * 4);
        float4 v3 = *(const float4*)(sb + (size_t)n3 * H_ + l * 4);
        d0 = fmaf(v0.x, a0, d0); d1 = fmaf(v0.y, a0, d1);
        d2 = fmaf(v0.z, a0, d2); d3 = fmaf(v0.w, a0, d3);
        d0 = fmaf(v1.x, a1, d0); d1 = fmaf(v1.y, a1, d1);
        d2 = fmaf(v1.z, a1, d2); d3 = fmaf(v1.w, a1, d3);
        d0 = fmaf(v2.x, a2, d0); d1 = fmaf(v2.y, a2, d1);
        d2 = fmaf(v2.z, a2, d2); d3 = fmaf(v2.w, a2, d3);
        d0 = fmaf(v3.x, a3, d0); d1 = fmaf(v3.y, a3, d1);
        d2 = fmaf(v3.z, a3, d2); d3 = fmaf(v3.w, a3, d3);
    }
    for (; it < cnt; ++it) {
        int n = nb[it];
        float a = attn_sh[n];
        float4 v = *(const float4*)(sb + (size_t)n * H_ + l * 4);
        d0 = fmaf(v.x, a, d0); d1 = fmaf(v.y, a, d1);
        d2 = fmaf(v.z, a, d2); d3 = fmaf(v.w, a, d3);
    }

    float scl = g_invdeg[m] * diff_scale[0];
    float ts = time_scale[0];
    float4 dyn = *(const float4*)(g_dyn + (size_t)row * H_ + l * 4);
    float dx0 = ts * (dyn.x + d0 * scl);
    float dx1 = ts * (dyn.y + d1 * scl);
    float dx2 = ts * (dyn.z + d2 * scl);
    float dx3 = ts * (dyn.w + d3 * scl);

    float sq = fmaf(dx0, dx0, fmaf(dx1, dx1, fmaf(dx2, dx2, dx3 * dx3)));
    float n2 = warp_sum_bcast(sq);
    float sc = fminf(10.0f / (sqrtf(n2) + 1e-8f), 1.0f);
    dx0 = sanf_(dx0 * sc); dx1 = sanf_(dx1 * sc);
    dx2 = sanf_(dx2 * sc); dx3 = sanf_(dx3 * sc);

    float4 so = *(const float4*)(g_sol + (size_t)p * ROWS * H_ + (size_t)row * H_ + l * 4);
    float sn0 = so.x + dx0 * DT_;
    float sn1 = so.y + dx1 * DT_;
    float sn2 = so.z + dx2 * DT_;
    float sn3 = so.w + dx3 * DT_;
    *(float4*)(g_sol + (size_t)(p + 1) * ROWS * H_ + (size_t)row * H_ + l * 4) =
        make_float4(sn0, sn1, sn2, sn3);
    float ss0 = sanf_(sn0), ss1 = sanf_(sn1), ss2 = sanf_(sn2), ss3 = sanf_(sn3);
    *(float4*)(ssan_next + (size_t)row * H_ + l * 4) = make_float4(ss0, ss1, ss2, ss3);

    float4 aw = *(const float4*)(attn_w + l * 4);
    float lp = fmaf(ss0, aw.x, fmaf(ss1, aw.y, fmaf(ss2, aw.z, ss3 * aw.w)));
    float lgt = warp_sum_bcast(lp);
    if (l == 0) g_logits[row] = lgt + attn_b[0];
}

// ---------------- kernel 5: frame GEMM (single launch, grid 1280) ----------------
__global__ __launch_bounds__(128) void frame_gemm_kernel(
    const float* __restrict__ w1, const float* __restrict__ b1)
{
    __shared__ float buf[64 * 128];
    int row0 = blockIdx.x << 6;
    int tid = threadIdx.x;
    {
        int r = tid >> 1, c0 = (tid & 1) << 6;
        const float4* pp = (const float4*)(g_sol + (size_t)(row0 + r) * H_ + c0);
        #pragma unroll
        for (int q = 0; q < 16; ++q) {
            float4 v = pp[q];
            int k = c0 + q * 4;
            buf[(k + 0) * 64 + r] = v.x;
            buf[(k + 1) * 64 + r] = v.y;
            buf[(k + 2) * 64 + r] = v.z;
            buf[(k + 3) * 64 + r] = v.w;
        }
    }
    __syncthreads();

    int tx = tid & 15, ty = tid >> 4;
    float acc[8][8];
    {
        float4 bi0 = *(const float4*)(b1 + tx * 8);
        float4 bi1 = *(const float4*)(b1 + tx * 8 + 4);
        #pragma unroll
        for (int i = 0; i < 8; ++i) {
            acc[i][0] = bi0.x; acc[i][1] = bi0.y; acc[i][2] = bi0.z; acc[i][3] = bi0.w;
            acc[i][4] = bi1.x; acc[i][5] = bi1.y; acc[i][6] = bi1.z; acc[i][7] = bi1.w;
        }
    }
    const float4* wv = (const float4*)w1;
    #pragma unroll 4
    for (int k = 0; k < H_; ++k) {
        float4 a0 = *(const float4*)&buf[k * 64 + ty * 8];
        float4 a1 = *(const float4*)&buf[k * 64 + ty * 8 + 4];
        float4 w0 = wv[k * 32 + tx * 2];
        float4 w1v = wv[k * 32 + tx * 2 + 1];
        float av[8] = {a0.x, a0.y, a0.z, a0.w, a1.x, a1.y, a1.z, a1.w};
        float bv[8] = {w0.x, w0.y, w0.z, w0.w, w1v.x, w1v.y, w1v.z, w1v.w};
        #pragma unroll
        for (int i = 0; i < 8; ++i)
            #pragma unroll
            for (int jj = 0; jj < 8; ++jj)
                acc[i][jj] = fmaf(av[i], bv[jj], acc[i][jj]);
    }
    #pragma unroll
    for (int i = 0; i < 8; ++i) {
        float4* dst = (float4*)&g_y[(size_t)(row0 + ty * 8 + i) * H_ + tx * 8];
        dst[0] = make_float4(acc[i][0], acc[i][1], acc[i][2], acc[i][3]);
        dst[1] = make_float4(acc[i][4], acc[i][5], acc[i][6], acc[i][7]);
    }
}

// ---------------- kernel 6: interval-major decoder ----------------
// grid = 9 intervals x 8 batches x 64 n-tiles = 4608 blocks, 128 threads.
// Thread (r=tid>>3, g=tid&7) owns row nt*16+r, cols g*16..g*16+15 — slices of
// Y[ic-1], Y[ic], sol[ic-1], sol[ic] held in REGISTERS across 7-8 s values.
__global__ __launch_bounds__(128) void decoder_interp_v2(
    const float* __restrict__ lgm, const float* __restrict__ lbt,
    const float* __restrict__ w2, const float* __restrict__ b2,
    float* __restrict__ out_pred, float* __restrict__ out_interp)
{
    __shared__ float wsm[H_ * C_];           // 8KB
    __shared__ float ppart[16 * 8 * 16];     // partial pred [r][g][c], 8KB
    __shared__ float prow[16 * 8], qrow[16 * 8];
    __shared__ float s_m[16], s_r[16];
    __shared__ float gl[H_], bl[H_];

    int blk = blockIdx.x;
    int tid = threadIdx.x;
    int nt = blk & 63;
    int b  = (blk >> 6) & 7;
    int ic = (blk >> 9) + 1;                 // 1..9

    int r = tid >> 3;                        // 0..15
    int g = tid & 7;                         // 0..7
    int c0 = g * 16;
    int n = nt * 16 + r;

    // stage w2 + LN params
    {
        const float4* w4 = (const float4*)w2;
        float4* d4 = (float4*)wsm;
        #pragma unroll
        for (int q = 0; q < 4; ++q) d4[tid * 4 + q] = w4[tid * 4 + q];
        gl[tid] = lgm[tid];
        bl[tid] = lbt[tid];
    }

    // per-thread register tiles
    float y0[16], y1[16], s0[16], s1[16];
    {
        size_t rowbase = ((size_t)b * N_ + n) * H_ + c0;
        const float4* py0 = (const float4*)(g_y  + (size_t)(ic - 1) * ROWS * H_ + rowbase);
        const float4* py1 = (const float4*)(g_y  + (size_t)ic * ROWS * H_ + rowbase);
        const float4* ps0 = (const float4*)(g_sol + (size_t)(ic - 1) * ROWS * H_ + rowbase);
        const float4* ps1 = (const float4*)(g_sol + (size_t)ic * ROWS * H_ + rowbase);
        #pragma unroll
        for (int q = 0; q < 4; ++q) {
            float4 v;
            v = py0[q]; y0[q*4+0]=v.x; y0[q*4+1]=v.y; y0[q*4+2]=v.z; y0[q*4+3]=v.w;
            v = py1[q]; y1[q*4+0]=v.x; y1[q*4+1]=v.y; y1[q*4+2]=v.z; y1[q*4+3]=v.w;
            v = ps0[q]; s0[q*4+0]=v.x; s0[q*4+1]=v.y; s0[q*4+2]=v.z; s0[q*4+3]=v.w;
            v = ps1[q]; s1[q*4+0]=v.x; s1[q*4+1]=v.y; s1[q*4+2]=v.z; s1[q*4+3]=v.w;
        }
    }
    __syncthreads();                          // wsm/gl/bl ready

    int s_start = (ic == 1) ? 0 : (7 * (ic - 1) + 1);
    int s_cnt   = (ic == 1) ? 8 : 7;

    for (int si = 0; si < s_cnt; ++si) {
        int s = s_start + si;
        float alpha = (float)(s - 7 * (ic - 1)) * (1.0f / 7.0f);
        float oma = 1.0f - alpha;

        // interp-Y + LN partials
        float yv[16];
        float sm = 0.0f, sq = 0.0f;
        #pragma unroll
        for (int i = 0; i < 16; ++i) {
            float v = oma * y0[i] + alpha * y1[i];
            yv[i] = v;
            sm += v;
            sq = fmaf(v, v, sq);
        }
        prow[r * 8 + g] = sm;
        qrow[r * 8 + g] = sq;

        // interp-sol output (write-once -> streaming)
        if (out_interp) {
            float4* po = (float4*)(out_interp + ((size_t)(s * B_ + b) * N_ + n) * H_ + c0);
            #pragma unroll
            for (int q = 0; q < 4; ++q) {
                float4 v = make_float4(
                    oma * s0[q*4+0] + alpha * s1[q*4+0],
                    oma * s0[q*4+1] + alpha * s1[q*4+1],
                    oma * s0[q*4+2] + alpha * s1[q*4+2],
                    oma * s0[q*4+3] + alpha * s1[q*4+3]);
                __stcs(po + q, v);
            }
        }
        __syncthreads();
        if (tid < 16) {
            float a = 0.0f, c = 0.0f;
            #pragma unroll
            for (int z = 0; z < 8; ++z) { a += prow[tid * 8 + z]; c += qrow[tid * 8 + z]; }
            float mean = a * (1.0f / H_);
            float var  = fmaxf(c * (1.0f / H_) - mean * mean, 0.0f);
            s_m[tid] = mean;
            s_r[tid] = rsqrtf(var + 1e-5f);
        }
        __syncthreads();

        // LN + SiLU + outer-product GEMM2 partials over this thread's 16 k values
        if (out_pred) {
            float m = s_m[r], rs = s_r[r];
            float part[16];
            #pragma unroll
            for (int c = 0; c < 16; ++c) part[c] = 0.0f;
            #pragma unroll
            for (int i = 0; i < 16; ++i) {
                int k = c0 + i;
                float h = siluf_((yv[i] - m) * rs * gl[k] + bl[k]);
                const float4* wrow = (const float4*)&wsm[k * C_];
                float4 w0v = wrow[0], w1v = wrow[1], w2v = wrow[2], w3v = wrow[3];
                part[0]  = fmaf(h, w0v.x, part[0]);  part[1]  = fmaf(h, w0v.y, part[1]);
                part[2]  = fmaf(h, w0v.z, part[2]);  part[3]  = fmaf(h, w0v.w, part[3]);
                part[4]  = fmaf(h, w1v.x, part[4]);  part[5]  = fmaf(h, w1v.y, part[5]);
                part[6]  = fmaf(h, w1v.z, part[6]);  part[7]  = fmaf(h, w1v.w, part[7]);
                part[8]  = fmaf(h, w2v.x, part[8]);  part[9]  = fmaf(h, w2v.y, part[9]);
                part[10] = fmaf(h, w2v.z, part[10]); part[11] = fmaf(h, w2v.w, part[11]);
                part[12] = fmaf(h, w3v.x, part[12]); part[13] = fmaf(h, w3v.y, part[13]);
                part[14] = fmaf(h, w3v.z, part[14]); part[15] = fmaf(h, w3v.w, part[15]);
            }
            float4* pd = (float4*)&ppart[(r * 8 + g) * 16];
            pd[0] = make_float4(part[0],  part[1],  part[2],  part[3]);
            pd[1] = make_float4(part[4],  part[5],  part[6],  part[7]);
            pd[2] = make_float4(part[8],  part[9],  part[10], part[11]);
            pd[3] = make_float4(part[12], part[13], part[14], part[15]);
        }
        __syncthreads();
        if (out_pred) {
            // thread outputs pred[r][2g], pred[r][2g+1]: fixed-order 8-way reduce
            int cc = g * 2;
            float a0 = b2[cc], a1 = b2[cc + 1];
            #pragma unroll
            for (int z = 0; z < 8; ++z) {
                a0 += ppart[(r * 8 + z) * 16 + cc];
                a1 += ppart[(r * 8 + z) * 16 + cc + 1];
            }
            float2* dst = (float2*)&out_pred[(((size_t)b * S_ + s) * N_ + n) * C_ + cc];
            __stcs(dst, make_float2(a0, a1));
        }
        __syncthreads();                      // protect prow/ppart before next s
    }
}

// ---------------- launch ----------------
extern "C" void kernel_launch(void* const* d_in, const int* in_sizes, int n_in,
                              void* d_out, int out_size)
{
    const float* x        = (const float*)d_in[0];
    const float* adj      = (const float*)d_in[1];
    const float* enc_w    = (const float*)d_in[2];
    const float* enc_b    = (const float*)d_in[3];
    const float* enc_g    = (const float*)d_in[4];
    const float* enc_beta = (const float*)d_in[5];
    const float* dyn_w1   = (const float*)d_in[6];
    const float* dyn_b1   = (const float*)d_in[7];
    const float* dyn_g    = (const float*)d_in[8];
    const float* dyn_beta = (const float*)d_in[9];
    const float* dyn_w2   = (const float*)d_in[10];
    const float* dyn_b2   = (const float*)d_in[11];
    const float* attn_w   = (const float*)d_in[12];
    const float* attn_b   = (const float*)d_in[13];
    const float* diff_sc  = (const float*)d_in[14];
    const float* time_sc  = (const float*)d_in[15];
    const float* dec_w1   = (const float*)d_in[16];
    const float* dec_b1   = (const float*)d_in[17];
    const float* dec_g    = (const float*)d_in[18];
    const float* dec_beta = (const float*)d_in[19];
    const float* dec_w2   = (const float*)d_in[20];
    const float* dec_b2   = (const float*)d_in[21];

    float* out = (float*)d_out;
    float* out_pred = nullptr;
    float* out_interp = nullptr;
    if (out_size >= PRED_ELEMS + INTERP_ELEMS) {
        out_pred = out;
        out_interp = out + PRED_ELEMS;
    } else if (out_size == PRED_ELEMS) {
        out_pred = out;
    } else if (out_size == INTERP_ELEMS) {
        out_interp = out;
    } else {
        out_pred = out;
    }

    build_graph_kernel<<<N_, 32>>>(adj);
    encoder_kernel<<<ROWS, 128>>>(x, enc_w, enc_b, enc_g, enc_beta, attn_w, attn_b);

    for (int p = 0; p < P_ - 1; ++p) {
        step_dyn_v4<<<ROWS / 32, 256>>>(p, dyn_w1, dyn_b1, dyn_g, dyn_beta,
                                        dyn_w2, dyn_b2);
        step_update_v2<<<ROWS / 4, 128>>>(p, diff_sc, time_sc, attn_w, attn_b);
    }

    frame_gemm_kernel<<<P_ * ROWS / 64, 128>>>(dec_w1, dec_b1);
    decoder_interp_v2<<<9 * 8 * 64, 128>>>(dec_g, dec_beta, dec_w2, dec_b2,
                                           out_pred, out_interp);
}

// round 17
// speedup vs baseline: 1.4876x; 1.4876x over previous
#include <cuda_runtime.h>
#include <math.h>
#include <stdint.h>

// ---------------- problem constants ----------------
#define B_   8
#define S_   64
#define N_   1024
#define C_   16
#define H_   128
#define P_   10
#define ROWS (B_ * N_)    // 8192
#define DT_  7.0f

#define PRED_ELEMS   (B_ * S_ * N_ * C_)       // 8388608
#define INTERP_ELEMS (S_ * B_ * N_ * H_)       // 67108864

// ---------------- device scratch ----------------
__device__ float g_sol[P_ * ROWS * H_];    // raw trajectory ~42MB
__device__ float g_ssan[2 * ROWS * H_];    // sanitized state, double-buffered
__device__ float g_y[P_ * ROWS * H_];      // sol@dec_w1+b1 ~42MB
__device__ float g_dyn[ROWS * H_];
__device__ float g_logits[ROWS];
__device__ float g_attn[ROWS];
__device__ int   g_nbr[N_ * N_];
__device__ int   g_cnt[N_];
__device__ float g_invdeg[N_];

// ---------------- helpers ----------------
__device__ __forceinline__ float sigmoidf_(float v) { return 1.0f / (1.0f + __expf(-v)); }
__device__ __forceinline__ float siluf_(float v)    { return v * sigmoidf_(v); }
__device__ __forceinline__ float tanh_fast(float x) {
    float y;
    asm("tanh.approx.f32 %0, %1;" : "=f"(y) : "f"(x));
    return y;
}
__device__ __forceinline__ float sanf_(float v) {
    if (isnan(v)) return 0.0f;
    if (isinf(v)) return v > 0.0f ? 3.402823466e38f : -3.402823466e38f;
    return v;
}

__device__ __forceinline__ float blk_sum128(float v, float* red) {
    #pragma unroll
    for (int o = 16; o > 0; o >>= 1) v += __shfl_down_sync(0xffffffffu, v, o);
    __syncthreads();
    if ((threadIdx.x & 31) == 0) red[threadIdx.x >> 5] = v;
    __syncthreads();
    return red[0] + red[1] + red[2] + red[3];
}

// 256-thread block reductions (red8 must hold >= 8 floats)
__device__ __forceinline__ float blk_sum256(float v, float* red8) {
    #pragma unroll
    for (int o = 16; o > 0; o >>= 1) v += __shfl_down_sync(0xffffffffu, v, o);
    __syncthreads();
    if ((threadIdx.x & 31) == 0) red8[threadIdx.x >> 5] = v;
    __syncthreads();
    float s = 0.0f;
    #pragma unroll
    for (int w = 0; w < 8; ++w) s += red8[w];
    return s;
}
__device__ __forceinline__ float blk_max256(float v, float* red8) {
    #pragma unroll
    for (int o = 16; o > 0; o >>= 1) v = fmaxf(v, __shfl_down_sync(0xffffffffu, v, o));
    __syncthreads();
    if ((threadIdx.x & 31) == 0) red8[threadIdx.x >> 5] = v;
    __syncthreads();
    float s = red8[0];
    #pragma unroll
    for (int w = 1; w < 8; ++w) s = fmaxf(s, red8[w]);
    return s;
}

// warp sum, deterministic tree, result broadcast to all lanes
__device__ __forceinline__ float warp_sum_bcast(float v) {
    #pragma unroll
    for (int o = 16; o > 0; o >>= 1) v += __shfl_down_sync(0xffffffffu, v, o);
    return __shfl_sync(0xffffffffu, v, 0);
}

// ---------------- kernel 1: adjacency -> neighbor lists ----------------
__global__ void build_graph_kernel(const float* __restrict__ adj) {
    int m = blockIdx.x;
    int l = threadIdx.x;
    float deg = 0.0f;
    int cnt = 0;
    for (int base = 0; base < N_; base += 32) {
        float a = adj[m * N_ + base + l];
        bool nz = (a != 0.0f);
        deg += a;
        unsigned mask = __ballot_sync(0xffffffffu, nz);
        int pre = __popc(mask & ((1u << l) - 1u));
        if (nz) g_nbr[m * N_ + cnt + pre] = base + l;
        cnt += __popc(mask);
    }
    #pragma unroll
    for (int o = 16; o > 0; o >>= 1) deg += __shfl_down_sync(0xffffffffu, deg, o);
    if (l == 0) {
        g_cnt[m] = cnt;
        g_invdeg[m] = 1.0f / (deg + 1e-8f);
    }
}

// ---------------- kernel 2: encoder -> sol[0], ssan[0], logits[0] ----------------
__global__ __launch_bounds__(128) void encoder_kernel(
    const float* __restrict__ x, const float* __restrict__ enc_w,
    const float* __restrict__ enc_b, const float* __restrict__ enc_g,
    const float* __restrict__ enc_beta,
    const float* __restrict__ attn_w, const float* __restrict__ attn_b)
{
    int row = blockIdx.x;
    int b = row >> 10, n = row & 1023;
    int j = threadIdx.x;
    __shared__ float xr[C_];
    __shared__ float red[4];
    if (j < C_) xr[j] = x[(size_t)b * (S_ * N_ * C_) + (size_t)n * C_ + j];
    __syncthreads();
    float acc = enc_b[j];
    #pragma unroll
    for (int c = 0; c < C_; ++c) acc = fmaf(xr[c], enc_w[c * H_ + j], acc);
    float mean = blk_sum128(acc, red) * (1.0f / H_);
    float d = acc - mean;
    float var = blk_sum128(d * d, red) * (1.0f / H_);
    float yn = d * rsqrtf(var + 1e-5f) * enc_g[j] + enc_beta[j];
    float z = siluf_(yn);
    g_sol[(size_t)row * H_ + j] = z;
    g_ssan[(size_t)row * H_ + j] = z;
    float lgt = blk_sum128(z * attn_w[j], red);
    if (j == 0) g_logits[row] = lgt + attn_b[0];
}

// ---------------- kernel 3: dyn MLP v4 (verified best: ~42.5us/step) ----------------
// grid 256. thread = (ty 0..7: 4 rows, kz 0..1: k-half, tx 0..15: 8 cols).
__global__ __launch_bounds__(256) void step_dyn_v4(
    int p,
    const float* __restrict__ w1, const float* __restrict__ b1,
    const float* __restrict__ lgm, const float* __restrict__ lbt,
    const float* __restrict__ w2, const float* __restrict__ b2)
{
    __shared__ float buf[32 * 132];
    __shared__ float psum[32 * 16];
    __shared__ float psq[32 * 16];
    __shared__ float s_mean[32];
    __shared__ float s_rstd[32];
    __shared__ float red8[8];

    int row0 = blockIdx.x << 5;
    int tid = threadIdx.x;
    int tx = tid & 15;
    int kz = (tid >> 4) & 1;
    int ty = tid >> 5;
    int kbase = kz << 6;

    const float* ssan = g_ssan + (size_t)(p & 1) * (ROWS * H_);

    if ((row0 & 1023) == 0) {
        int b = row0 >> 10;
        const float* lg = &g_logits[b * N_];
        float lv[4];
        float mloc = -INFINITY;
        #pragma unroll
        for (int i = 0; i < 4; ++i) { lv[i] = lg[tid + i * 256]; mloc = fmaxf(mloc, lv[i]); }
        float mx = blk_max256(mloc, red8);
        float sloc = 0.0f;
        #pragma unroll
        for (int i = 0; i < 4; ++i) { lv[i] = expf(lv[i] - mx); sloc += lv[i]; }
        float tot = blk_sum256(sloc, red8);
        float inv = 1.0f / tot;
        #pragma unroll
        for (int i = 0; i < 4; ++i) g_attn[b * N_ + tid + i * 256] = lv[i] * inv;
    }

    {
        int r = tid >> 3, c0 = (tid & 7) << 4;
        const float4* pp = (const float4*)(ssan + (size_t)(row0 + r) * H_ + c0);
        #pragma unroll
        for (int q = 0; q < 4; ++q) {
            float4 v = pp[q];
            int k = c0 + q * 4;
            buf[(k + 0) * 32 + r] = v.x;
            buf[(k + 1) * 32 + r] = v.y;
            buf[(k + 2) * 32 + r] = v.z;
            buf[(k + 3) * 32 + r] = v.w;
        }
    }
    __syncthreads();

    float acc[4][8];
    if (kz == 0) {
        float4 bi0 = *(const float4*)(b1 + tx * 8);
        float4 bi1 = *(const float4*)(b1 + tx * 8 + 4);
        #pragma unroll
        for (int i = 0; i < 4; ++i) {
            acc[i][0] = bi0.x; acc[i][1] = bi0.y; acc[i][2] = bi0.z; acc[i][3] = bi0.w;
            acc[i][4] = bi1.x; acc[i][5] = bi1.y; acc[i][6] = bi1.z; acc[i][7] = bi1.w;
        }
    } else {
        #pragma unroll
        for (int i = 0; i < 4; ++i)
            #pragma unroll
            for (int j = 0; j < 8; ++j) acc[i][j] = 0.0f;
    }
    const float4* wv = (const float4*)w1;
    #pragma unroll 4
    for (int k = 0; k < 64; ++k) {
        int kk = kbase + k;
        float4 a0 = *(const float4*)&buf[kk * 32 + ty * 4];
        float4 w0 = wv[kk * 32 + tx * 2];
        float4 w1v = wv[kk * 32 + tx * 2 + 1];
        float av[4] = {a0.x, a0.y, a0.z, a0.w};
        float bv[8] = {w0.x, w0.y, w0.z, w0.w, w1v.x, w1v.y, w1v.z, w1v.w};
        #pragma unroll
        for (int i = 0; i < 4; ++i)
            #pragma unroll
            for (int j = 0; j < 8; ++j)
                acc[i][j] = fmaf(av[i], bv[j], acc[i][j]);
    }
    __syncthreads();
    if (kz == 1) {
        #pragma unroll
        for (int i = 0; i < 4; ++i) {
            float4* dst = (float4*)&buf[(ty * 4 + i) * 132 + tx * 8];
            dst[0] = make_float4(acc[i][0], acc[i][1], acc[i][2], acc[i][3]);
            dst[1] = make_float4(acc[i][4], acc[i][5], acc[i][6], acc[i][7]);
        }
    }
    __syncthreads();
    if (kz == 0) {
        #pragma unroll
        for (int i = 0; i < 4; ++i) {
            const float4* src = (const float4*)&buf[(ty * 4 + i) * 132 + tx * 8];
            float4 p0 = src[0], p1 = src[1];
            acc[i][0] += p0.x; acc[i][1] += p0.y; acc[i][2] += p0.z; acc[i][3] += p0.w;
            acc[i][4] += p1.x; acc[i][5] += p1.y; acc[i][6] += p1.z; acc[i][7] += p1.w;
            float sm = 0.0f, sq = 0.0f;
            #pragma unroll
            for (int j = 0; j < 8; ++j) { sm += acc[i][j]; sq = fmaf(acc[i][j], acc[i][j], sq); }
            psum[(ty * 4 + i) * 16 + tx] = sm;
            psq [(ty * 4 + i) * 16 + tx] = sq;
        }
    }
    __syncthreads();
    if (tid < 32) {
        float sm = 0.0f, sq = 0.0f;
        #pragma unroll
        for (int t = 0; t < 16; ++t) { sm += psum[tid * 16 + t]; sq += psq[tid * 16 + t]; }
        float mean = sm * (1.0f / H_);
        float var  = fmaxf(sq * (1.0f / H_) - mean * mean, 0.0f);
        s_mean[tid] = mean;
        s_rstd[tid] = rsqrtf(var + 1e-5f);
    }
    __syncthreads();

    if (kz == 0) {
        float4 g0 = *(const float4*)(lgm + tx * 8);
        float4 g1 = *(const float4*)(lgm + tx * 8 + 4);
        float4 e0 = *(const float4*)(lbt + tx * 8);
        float4 e1 = *(const float4*)(lbt + tx * 8 + 4);
        float gj[8] = {g0.x, g0.y, g0.z, g0.w, g1.x, g1.y, g1.z, g1.w};
        float ej[8] = {e0.x, e0.y, e0.z, e0.w, e1.x, e1.y, e1.z, e1.w};
        #pragma unroll
        for (int i = 0; i < 4; ++i) {
            int r = ty * 4 + i;
            float m = s_mean[r], rs = s_rstd[r];
            float hv[8];
            #pragma unroll
            for (int j = 0; j < 8; ++j)
                hv[j] = siluf_((acc[i][j] - m) * rs * gj[j] + ej[j]);
            float4* dst = (float4*)&buf[r * 132 + tx * 8];
            dst[0] = make_float4(hv[0], hv[1], hv[2], hv[3]);
            dst[1] = make_float4(hv[4], hv[5], hv[6], hv[7]);
        }
    }
    __syncthreads();

    if (kz == 0) {
        float4 bi0 = *(const float4*)(b2 + tx * 8);
        float4 bi1 = *(const float4*)(b2 + tx * 8 + 4);
        #pragma unroll
        for (int i = 0; i < 4; ++i) {
            acc[i][0] = bi0.x; acc[i][1] = bi0.y; acc[i][2] = bi0.z; acc[i][3] = bi0.w;
            acc[i][4] = bi1.x; acc[i][5] = bi1.y; acc[i][6] = bi1.z; acc[i][7] = bi1.w;
        }
    } else {
        #pragma unroll
        for (int i = 0; i < 4; ++i)
            #pragma unroll
            for (int j = 0; j < 8; ++j) acc[i][j] = 0.0f;
    }
    const float4* wv2 = (const float4*)w2;
    #pragma unroll 4
    for (int k = 0; k < 64; ++k) {
        int kk = kbase + k;
        float4 w0 = wv2[kk * 32 + tx * 2];
        float4 w1v = wv2[kk * 32 + tx * 2 + 1];
        float bv[8] = {w0.x, w0.y, w0.z, w0.w, w1v.x, w1v.y, w1v.z, w1v.w};
        float av[4];
        #pragma unroll
        for (int i = 0; i < 4; ++i) av[i] = buf[(ty * 4 + i) * 132 + kk];
        #pragma unroll
        for (int i = 0; i < 4; ++i)
            #pragma unroll
            for (int j = 0; j < 8; ++j)
                acc[i][j] = fmaf(av[i], bv[j], acc[i][j]);
    }
    __syncthreads();
    if (kz == 1) {
        #pragma unroll
        for (int i = 0; i < 4; ++i) {
            float4* dst = (float4*)&buf[(ty * 4 + i) * 132 + tx * 8];
            dst[0] = make_float4(acc[i][0], acc[i][1], acc[i][2], acc[i][3]);
            dst[1] = make_float4(acc[i][4], acc[i][5], acc[i][6], acc[i][7]);
        }
    }
    __syncthreads();
    if (kz == 0) {
        #pragma unroll
        for (int i = 0; i < 4; ++i) {
            const float4* src = (const float4*)&buf[(ty * 4 + i) * 132 + tx * 8];
            float4 p0 = src[0], p1 = src[1];
            float o[8];
            o[0] = tanh_fast(acc[i][0] + p0.x);
            o[1] = tanh_fast(acc[i][1] + p0.y);
            o[2] = tanh_fast(acc[i][2] + p0.z);
            o[3] = tanh_fast(acc[i][3] + p0.w);
            o[4] = tanh_fast(acc[i][4] + p1.x);
            o[5] = tanh_fast(acc[i][5] + p1.y);
            o[6] = tanh_fast(acc[i][6] + p1.z);
            o[7] = tanh_fast(acc[i][7] + p1.w);
            float4* dst = (float4*)&g_dyn[(size_t)(row0 + ty * 4 + i) * H_ + tx * 8];
            dst[0] = make_float4(o[0], o[1], o[2], o[3]);
            dst[1] = make_float4(o[4], o[5], o[6], o[7]);
        }
    }
}

// ---------------- kernel 4: update, warp-per-row (grid 2048) ----------------
__global__ __launch_bounds__(128) void step_update_v2(
    int p, const float* __restrict__ diff_scale, const float* __restrict__ time_scale,
    const float* __restrict__ attn_w, const float* __restrict__ attn_b)
{
    __shared__ float attn_sh[N_];

    int row0 = blockIdx.x << 2;
    int b = row0 >> 10;
    int tid = threadIdx.x;
    int w = tid >> 5;
    int l = tid & 31;

    {
        const float4* src = (const float4*)(g_attn + b * N_);
        float4* dst = (float4*)attn_sh;
        for (int i = tid; i < N_ / 4; i += 128) dst[i] = src[i];
    }
    __syncthreads();

    const float* ssan = g_ssan + (size_t)(p & 1) * (ROWS * H_);
    float* ssan_next  = g_ssan + (size_t)((p + 1) & 1) * (ROWS * H_);

    int row = row0 + w;
    int m = row & 1023;
    int cnt = g_cnt[m];
    const int* nb = &g_nbr[m * N_];
    const float* sb = ssan + (size_t)b * N_ * H_;

    float d0 = 0.0f, d1 = 0.0f, d2 = 0.0f, d3 = 0.0f;
    int it = 0;
    for (; it + 4 <= cnt; it += 4) {
        int n0 = nb[it], n1 = nb[it + 1], n2 = nb[it + 2], n3 = nb[it + 3];
        float a0 = attn_sh[n0], a1 = attn_sh[n1], a2 = attn_sh[n2], a3 = attn_sh[n3];
        float4 v0 = *(const float4*)(sb + (size_t)n0 * H_ + l * 4);
        float4 v1 = *(const float4*)(sb + (size_t)n1 * H_ + l * 4);
        float4 v2 = *(const float4*)(sb + (size_t)n2 * H_ + l * 4);
        float4 v3 = *(const float4*)(sb + (size_t)n3 * H_ + l * 4);
        d0 = fmaf(v0.x, a0, d0); d1 = fmaf(v0.y, a0, d1);
        d2 = fmaf(v0.z, a0, d2); d3 = fmaf(v0.w, a0, d3);
        d0 = fmaf(v1.x, a1, d0); d1 = fmaf(v1.y, a1, d1);
        d2 = fmaf(v1.z, a1, d2); d3 = fmaf(v1.w, a1, d3);
        d0 = fmaf(v2.x, a2, d0); d1 = fmaf(v2.y, a2, d1);
        d2 = fmaf(v2.z, a2, d2); d3 = fmaf(v2.w, a2, d3);
        d0 = fmaf(v3.x, a3, d0); d1 = fmaf(v3.y, a3, d1);
        d2 = fmaf(v3.z, a3, d2); d3 = fmaf(v3.w, a3, d3);
    }
    for (; it < cnt; ++it) {
        int n = nb[it];
        float a = attn_sh[n];
        float4 v = *(const float4*)(sb + (size_t)n * H_ + l * 4);
        d0 = fmaf(v.x, a, d0); d1 = fmaf(v.y, a, d1);
        d2 = fmaf(v.z, a, d2); d3 = fmaf(v.w, a, d3);
    }

    float scl = g_invdeg[m] * diff_scale[0];
    float ts = time_scale[0];
    float4 dyn = *(const float4*)(g_dyn + (size_t)row * H_ + l * 4);
    float dx0 = ts * (dyn.x + d0 * scl);
    float dx1 = ts * (dyn.y + d1 * scl);
    float dx2 = ts * (dyn.z + d2 * scl);
    float dx3 = ts * (dyn.w + d3 * scl);

    float sq = fmaf(dx0, dx0, fmaf(dx1, dx1, fmaf(dx2, dx2, dx3 * dx3)));
    float n2 = warp_sum_bcast(sq);
    float sc = fminf(10.0f / (sqrtf(n2) + 1e-8f), 1.0f);
    dx0 = sanf_(dx0 * sc); dx1 = sanf_(dx1 * sc);
    dx2 = sanf_(dx2 * sc); dx3 = sanf_(dx3 * sc);

    float4 so = *(const float4*)(g_sol + (size_t)p * ROWS * H_ + (size_t)row * H_ + l * 4);
    float sn0 = so.x + dx0 * DT_;
    float sn1 = so.y + dx1 * DT_;
    float sn2 = so.z + dx2 * DT_;
    float sn3 = so.w + dx3 * DT_;
    *(float4*)(g_sol + (size_t)(p + 1) * ROWS * H_ + (size_t)row * H_ + l * 4) =
        make_float4(sn0, sn1, sn2, sn3);
    float ss0 = sanf_(sn0), ss1 = sanf_(sn1), ss2 = sanf_(sn2), ss3 = sanf_(sn3);
    *(float4*)(ssan_next + (size_t)row * H_ + l * 4) = make_float4(ss0, ss1, ss2, ss3);

    float4 aw = *(const float4*)(attn_w + l * 4);
    float lp = fmaf(ss0, aw.x, fmaf(ss1, aw.y, fmaf(ss2, aw.z, ss3 * aw.w)));
    float lgt = warp_sum_bcast(lp);
    if (l == 0) g_logits[row] = lgt + attn_b[0];
}

// ---------------- kernel 5: frame GEMM (single launch, grid 1280) ----------------
__global__ __launch_bounds__(128) void frame_gemm_kernel(
    const float* __restrict__ w1, const float* __restrict__ b1)
{
    __shared__ float buf[64 * 128];
    int row0 = blockIdx.x << 6;
    int tid = threadIdx.x;
    {
        int r = tid >> 1, c0 = (tid & 1) << 6;
        const float4* pp = (const float4*)(g_sol + (size_t)(row0 + r) * H_ + c0);
        #pragma unroll
        for (int q = 0; q < 16; ++q) {
            float4 v = pp[q];
            int k = c0 + q * 4;
            buf[(k + 0) * 64 + r] = v.x;
            buf[(k + 1) * 64 + r] = v.y;
            buf[(k + 2) * 64 + r] = v.z;
            buf[(k + 3) * 64 + r] = v.w;
        }
    }
    __syncthreads();

    int tx = tid & 15, ty = tid >> 4;
    float acc[8][8];
    {
        float4 bi0 = *(const float4*)(b1 + tx * 8);
        float4 bi1 = *(const float4*)(b1 + tx * 8 + 4);
        #pragma unroll
        for (int i = 0; i < 8; ++i) {
            acc[i][0] = bi0.x; acc[i][1] = bi0.y; acc[i][2] = bi0.z; acc[i][3] = bi0.w;
            acc[i][4] = bi1.x; acc[i][5] = bi1.y; acc[i][6] = bi1.z; acc[i][7] = bi1.w;
        }
    }
    const float4* wv = (const float4*)w1;
    #pragma unroll 4
    for (int k = 0; k < H_; ++k) {
        float4 a0 = *(const float4*)&buf[k * 64 + ty * 8];
        float4 a1 = *(const float4*)&buf[k * 64 + ty * 8 + 4];
        float4 w0 = wv[k * 32 + tx * 2];
        float4 w1v = wv[k * 32 + tx * 2 + 1];
        float av[8] = {a0.x, a0.y, a0.z, a0.w, a1.x, a1.y, a1.z, a1.w};
        float bv[8] = {w0.x, w0.y, w0.z, w0.w, w1v.x, w1v.y, w1v.z, w1v.w};
        #pragma unroll
        for (int i = 0; i < 8; ++i)
            #pragma unroll
            for (int jj = 0; jj < 8; ++jj)
                acc[i][jj] = fmaf(av[i], bv[jj], acc[i][jj]);
    }
    #pragma unroll
    for (int i = 0; i < 8; ++i) {
        float4* dst = (float4*)&g_y[(size_t)(row0 + ty * 8 + i) * H_ + tx * 8];
        dst[0] = make_float4(acc[i][0], acc[i][1], acc[i][2], acc[i][3]);
        dst[1] = make_float4(acc[i][4], acc[i][5], acc[i][6], acc[i][7]);
    }
}

// ---------------- kernel 6: interp(Y) + LN + SiLU + GEMM2 + outputs ----------------
__global__ __launch_bounds__(128) void decoder_interp_kernel(
    const float* __restrict__ lgm, const float* __restrict__ lbt,
    const float* __restrict__ w2, const float* __restrict__ b2,
    float* __restrict__ out_pred, float* __restrict__ out_interp)
{
    __shared__ float buf[64 * 132];
    __shared__ float psum[128], psq[128];
    __shared__ float s_mean[64], s_rstd[64];
    __shared__ float gl[H_], bl[H_];

    int blk = blockIdx.x;
    int tid = threadIdx.x;
    int n0 = (blk & 15) << 6;
    int sb = blk >> 4;
    int b  = sb & 7;
    int s  = sb >> 3;

    gl[tid] = lgm[tid];
    bl[tid] = lbt[tid];

    int ic = (s + 6) / 7;
    if (ic < 1) ic = 1;
    if (ic > P_ - 1) ic = P_ - 1;
    float alpha = (float)(s - 7 * (ic - 1)) * (1.0f / 7.0f);
    float oma = 1.0f - alpha;

    {
        int r = tid >> 1, c0 = (tid & 1) << 6;
        size_t rowbase = ((size_t)b * N_ + (n0 + r)) * H_ + c0;
        const float4* y0p = (const float4*)(g_y + (size_t)(ic - 1) * ROWS * H_ + rowbase);
        const float4* y1p = (const float4*)(g_y + (size_t)ic * ROWS * H_ + rowbase);
        float sm = 0.0f, sq = 0.0f;
        #pragma unroll
        for (int q = 0; q < 16; ++q) {
            float4 v0 = y0p[q], v1 = y1p[q];
            float4 yv;
            yv.x = oma * v0.x + alpha * v1.x;
            yv.y = oma * v0.y + alpha * v1.y;
            yv.z = oma * v0.z + alpha * v1.z;
            yv.w = oma * v0.w + alpha * v1.w;
            sm += yv.x + yv.y + yv.z + yv.w;
            sq = fmaf(yv.x, yv.x, sq); sq = fmaf(yv.y, yv.y, sq);
            sq = fmaf(yv.z, yv.z, sq); sq = fmaf(yv.w, yv.w, sq);
            *(float4*)&buf[r * 132 + c0 + q * 4] = yv;
        }
        psum[r * 2 + (tid & 1)] = sm;
        psq [r * 2 + (tid & 1)] = sq;

        if (out_interp) {
            const float4* s0p = (const float4*)(g_sol + (size_t)(ic - 1) * ROWS * H_ + rowbase);
            const float4* s1p = (const float4*)(g_sol + (size_t)ic * ROWS * H_ + rowbase);
            float4* po = (float4*)(out_interp + ((size_t)(s * B_ + b) * N_ + (n0 + r)) * H_ + c0);
            #pragma unroll
            for (int q = 0; q < 16; ++q) {
                float4 v0 = s0p[q], v1 = s1p[q];
                float4 iv;
                iv.x = oma * v0.x + alpha * v1.x;
                iv.y = oma * v0.y + alpha * v1.y;
                iv.z = oma * v0.z + alpha * v1.z;
                iv.w = oma * v0.w + alpha * v1.w;
                __stcs(po + q, iv);
            }
        }
    }
    __syncthreads();

    if (tid < 64) {
        float sm = psum[tid * 2] + psum[tid * 2 + 1];
        float sq = psq[tid * 2] + psq[tid * 2 + 1];
        float mean = sm * (1.0f / H_);
        float var  = fmaxf(sq * (1.0f / H_) - mean * mean, 0.0f);
        s_mean[tid] = mean;
        s_rstd[tid] = rsqrtf(var + 1e-5f);
    }
    __syncthreads();

    {
        int r = tid >> 1, c0 = (tid & 1) << 6;
        float m = s_mean[r], rs = s_rstd[r];
        #pragma unroll
        for (int q = 0; q < 16; ++q) {
            int k = c0 + q * 4;
            float4 yv = *(float4*)&buf[r * 132 + k];
            yv.x = siluf_((yv.x - m) * rs * gl[k + 0] + bl[k + 0]);
            yv.y = siluf_((yv.y - m) * rs * gl[k + 1] + bl[k + 1]);
            yv.z = siluf_((yv.z - m) * rs * gl[k + 2] + bl[k + 2]);
            yv.w = siluf_((yv.w - m) * rs * gl[k + 3] + bl[k + 3]);
            *(float4*)&buf[r * 132 + k] = yv;
        }
    }
    __syncthreads();

    if (out_pred) {
        int c0 = (tid & 3) * 4;
        int rg = tid >> 2;
        float4 bb = *(const float4*)(b2 + c0);
        float acc2[2][4];
        #pragma unroll
        for (int r = 0; r < 2; ++r) {
            acc2[r][0] = bb.x; acc2[r][1] = bb.y; acc2[r][2] = bb.z; acc2[r][3] = bb.w;
        }
        #pragma unroll 4
        for (int k4 = 0; k4 < 32; ++k4) {
            int k = k4 * 4;
            float4 wr0 = *(const float4*)(w2 + (k + 0) * C_ + c0);
            float4 wr1 = *(const float4*)(w2 + (k + 1) * C_ + c0);
            float4 wr2 = *(const float4*)(w2 + (k + 2) * C_ + c0);
            float4 wr3 = *(const float4*)(w2 + (k + 3) * C_ + c0);
            #pragma unroll
            for (int r = 0; r < 2; ++r) {
                float4 av = *(const float4*)&buf[(rg * 2 + r) * 132 + k];
                acc2[r][0] = fmaf(av.x, wr0.x, acc2[r][0]);
                acc2[r][1] = fmaf(av.x, wr0.y, acc2[r][1]);
                acc2[r][2] = fmaf(av.x, wr0.z, acc2[r][2]);
                acc2[r][3] = fmaf(av.x, wr0.w, acc2[r][3]);
                acc2[r][0] = fmaf(av.y, wr1.x, acc2[r][0]);
                acc2[r][1] = fmaf(av.y, wr1.y, acc2[r][1]);
                acc2[r][2] = fmaf(av.y, wr1.z, acc2[r][2]);
                acc2[r][3] = fmaf(av.y, wr1.w, acc2[r][3]);
                acc2[r][0] = fmaf(av.z, wr2.x, acc2[r][0]);
                acc2[r][1] = fmaf(av.z, wr2.y, acc2[r][1]);
                acc2[r][2] = fmaf(av.z, wr2.z, acc2[r][2]);
                acc2[r][3] = fmaf(av.z, wr2.w, acc2[r][3]);
                acc2[r][0] = fmaf(av.w, wr3.x, acc2[r][0]);
                acc2[r][1] = fmaf(av.w, wr3.y, acc2[r][1]);
                acc2[r][2] = fmaf(av.w, wr3.z, acc2[r][2]);
                acc2[r][3] = fmaf(av.w, wr3.w, acc2[r][3]);
            }
        }
        #pragma unroll
        for (int r = 0; r < 2; ++r) {
            int n = n0 + rg * 2 + r;
            float4* dst = (float4*)&out_pred[(((size_t)b * S_ + s) * N_ + n) * C_ + c0];
            __stcs(dst, make_float4(acc2[r][0], acc2[r][1], acc2[r][2], acc2[r][3]));
        }
    }
}

// ---------------- launch ----------------
extern "C" void kernel_launch(void* const* d_in, const int* in_sizes, int n_in,
                              void* d_out, int out_size)
{
    const float* x        = (const float*)d_in[0];
    const float* adj      = (const float*)d_in[1];
    const float* enc_w    = (const float*)d_in[2];
    const float* enc_b    = (const float*)d_in[3];
    const float* enc_g    = (const float*)d_in[4];
    const float* enc_beta = (const float*)d_in[5];
    const float* dyn_w1   = (const float*)d_in[6];
    const float* dyn_b1   = (const float*)d_in[7];
    const float* dyn_g    = (const float*)d_in[8];
    const float* dyn_beta = (const float*)d_in[9];
    const float* dyn_w2   = (const float*)d_in[10];
    const float* dyn_b2   = (const float*)d_in[11];
    const float* attn_w   = (const float*)d_in[12];
    const float* attn_b   = (const float*)d_in[13];
    const float* diff_sc  = (const float*)d_in[14];
    const float* time_sc  = (const float*)d_in[15];
    const float* dec_w1   = (const float*)d_in[16];
    const float* dec_b1   = (const float*)d_in[17];
    const float* dec_g    = (const float*)d_in[18];
    const float* dec_beta = (const float*)d_in[19];
    const float* dec_w2   = (const float*)d_in[20];
    const float* dec_b2   = (const float*)d_in[21];

    float* out = (float*)d_out;
    float* out_pred = nullptr;
    float* out_interp = nullptr;
    if (out_size >= PRED_ELEMS + INTERP_ELEMS) {
        out_pred = out;
        out_interp = out + PRED_ELEMS;
    } else if (out_size == PRED_ELEMS) {
        out_pred = out;
    } else if (out_size == INTERP_ELEMS) {
        out_interp = out;
    } else {
        out_pred = out;
    }

    build_graph_kernel<<<N_, 32>>>(adj);
    encoder_kernel<<<ROWS, 128>>>(x, enc_w, enc_b, enc_g, enc_beta, attn_w, attn_b);

    for (int p = 0; p < P_ - 1; ++p) {
        step_dyn_v4<<<ROWS / 32, 256>>>(p, dyn_w1, dyn_b1, dyn_g, dyn_beta,
                                        dyn_w2, dyn_b2);
        step_update_v2<<<ROWS / 4, 128>>>(p, diff_sc, time_sc, attn_w, attn_b);
    }

    frame_gemm_kernel<<<P_ * ROWS / 64, 128>>>(dec_w1, dec_b1);
    decoder_interp_kernel<<<S_ * B_ * N_ / 64, 128>>>(dec_g, dec_beta, dec_w2, dec_b2,
                                                      out_pred, out_interp);
}